// round 17
// baseline (speedup 1.0000x reference)
#include <cuda_runtime.h>
#include <cuda_bf16.h>
#include <cstdint>

// Problem constants (compile-time for __device__ scratch sizing)
constexpr int NN = 50000;   // nodes
constexpr int EE = 800000;  // edges
constexpr int F  = 128;     // feature dim
constexpr int SCAN_B = 1024;

// ---------------- scratch (device globals; no allocation allowed) -----------
__device__ float g_bufA[NN * F];    // tmp' buffers (ping-pong)
__device__ float g_bufB[NN * F];
__device__ float g_dis[NN];         // deg^{-1/2}
__device__ int   g_cnt[NN];         // in-edge count (excl. self loop)
__device__ int   g_rowstart[NN];    // CSR row offsets
__device__ int   g_cursor[NN];      // fill cursors
__device__ int   g_csrc[EE];        // CSR src indices grouped by dst
__device__ int   g_blocksum[256];
__device__ int   g_blockoff[256];
// W in mma.sync B-fragment layout: [layer][0=hi,1=lo][kstep][ntile][lane]
__device__ uint2 g_wfrag[3][2][8][16][32];

// ---------------- degree / CSR build ----------------------------------------
__global__ void init_cnt_kernel(int n) {
    int i = blockIdx.x * blockDim.x + threadIdx.x;
    if (i < n) g_cnt[i] = 0;
}

__global__ void count_kernel(const int* __restrict__ ei, int E) {
    int e = blockIdx.x * blockDim.x + threadIdx.x;
    if (e < E) atomicAdd(&g_cnt[ei[E + e]], 1);
}

__global__ __launch_bounds__(SCAN_B) void scan_blocks_kernel(int n) {
    __shared__ int warpsum[32];
    int tid = threadIdx.x, lane = tid & 31, wid = tid >> 5;
    int i = blockIdx.x * SCAN_B + tid;
    int v = (i < n) ? g_cnt[i] : 0;
    if (i < n) g_dis[i] = rsqrtf(1.0f + (float)v);

    int x = v;
    #pragma unroll
    for (int o = 1; o < 32; o <<= 1) {
        int y = __shfl_up_sync(0xFFFFFFFFu, x, o);
        if (lane >= o) x += y;
    }
    if (lane == 31) warpsum[wid] = x;
    __syncthreads();
    if (wid == 0) {
        int w = warpsum[lane];
        #pragma unroll
        for (int o = 1; o < 32; o <<= 1) {
            int y = __shfl_up_sync(0xFFFFFFFFu, w, o);
            if (lane >= o) w += y;
        }
        warpsum[lane] = w;
    }
    __syncthreads();
    int excl = (x - v) + (wid ? warpsum[wid - 1] : 0);
    if (i < n) g_rowstart[i] = excl;
    if (tid == SCAN_B - 1) g_blocksum[blockIdx.x] = warpsum[31];
}

__global__ __launch_bounds__(256) void scan_sums_kernel(int nblk) {
    __shared__ int warpsum[8];
    int tid = threadIdx.x, lane = tid & 31, wid = tid >> 5;
    int v = (tid < nblk) ? g_blocksum[tid] : 0;
    int x = v;
    #pragma unroll
    for (int o = 1; o < 32; o <<= 1) {
        int y = __shfl_up_sync(0xFFFFFFFFu, x, o);
        if (lane >= o) x += y;
    }
    if (lane == 31) warpsum[wid] = x;
    __syncthreads();
    int woff = 0;
    for (int w = 0; w < wid; w++) woff += warpsum[w];
    if (tid < nblk) g_blockoff[tid] = (x - v) + woff;
}

__global__ __launch_bounds__(SCAN_B) void scan_add_kernel(int n) {
    int i = blockIdx.x * SCAN_B + threadIdx.x;
    if (i >= n) return;
    int r = g_rowstart[i] + g_blockoff[blockIdx.x];
    g_rowstart[i] = r;
    g_cursor[i] = r;
}

__global__ void fill_kernel(const int* __restrict__ ei, int E) {
    int e = blockIdx.x * blockDim.x + threadIdx.x;
    if (e >= E) return;
    int s = ei[e];
    int d = ei[E + e];
    int pos = atomicAdd(&g_cursor[d], 1);
    g_csrc[pos] = s;
}

// ---------------- W fragment pre-bake ----------------------------------------
__device__ __forceinline__ uint32_t pack_bf2(__nv_bfloat16 lo16, __nv_bfloat16 hi16) {
    __nv_bfloat162 p;
    p.x = lo16; p.y = hi16;
    return *(uint32_t*)&p;
}

__global__ void wfrag_kernel(const float* __restrict__ Ws) {
    int i = blockIdx.x * blockDim.x + threadIdx.x;   // over 3*2*8*16*32 = 24576
    if (i >= 3 * 2 * 8 * 16 * 32) return;
    int lane = i & 31; int t = i >> 5;
    int nt = t & 15; t >>= 4;
    int ks = t & 7;  t >>= 3;
    int termB = t & 1;
    int l = t >> 1;
    int nn = nt * 8 + (lane >> 2);

    uint32_t regs[2];
    #pragma unroll
    for (int r = 0; r < 2; r++) {
        int k = ks * 16 + (lane & 3) * 2 + r * 8;
        float w0 = Ws[l * F * F + k * F + nn];
        float w1 = Ws[l * F * F + (k + 1) * F + nn];
        __nv_bfloat16 h0 = __float2bfloat16(w0);
        __nv_bfloat16 h1 = __float2bfloat16(w1);
        __nv_bfloat16 v0, v1;
        if (termB == 0) { v0 = h0; v1 = h1; }
        else {
            v0 = __float2bfloat16(w0 - __bfloat162float(h0));
            v1 = __float2bfloat16(w1 - __bfloat162float(h1));
        }
        regs[r] = pack_bf2(v0, v1);
    }
    g_wfrag[l][termB][ks][nt][lane] = make_uint2(regs[0], regs[1]);
}

// ---------------- fused gather + tensor-core GEMM ----------------------------
// bufsel: 0 -> in=g_bufA, out=g_bufB ; 1 -> in=g_bufB, out=g_bufA
// GATHER=true : out = dis * ( elu(dis*AGG(in) + bias) @ W )
// GATHER=false: out(g_bufA) = dis * ( Ain @ W )   (layer 0, Ain = x)
// mma.sync.m16n8k16 bf16, 3-term split precision (HH + HL + LH).
// CTA: BM=64 rows, 8 warps = 2(M) x 4(N); warp tile 32x32.
constexpr int LDA = 136;   // smem row stride in bf16 units (272B, conflict-free)

__device__ __forceinline__ float elu_act(float v) {
    return v > 0.0f ? v : expm1f(v);
}

__device__ __forceinline__ uint32_t smem_u32(const void* p) {
    uint32_t a;
    asm("{ .reg .u64 t; cvta.to.shared.u64 t, %1; cvt.u32.u64 %0, t; }"
        : "=r"(a) : "l"(p));
    return a;
}

__device__ __forceinline__ void split_store(
    __nv_bfloat16* sAhi, __nv_bfloat16* sAlo, int off, float4 v)
{
    __nv_bfloat16 hx = __float2bfloat16(v.x);
    __nv_bfloat16 hy = __float2bfloat16(v.y);
    __nv_bfloat16 hz = __float2bfloat16(v.z);
    __nv_bfloat16 hw = __float2bfloat16(v.w);
    uint2 hv, lv;
    hv.x = pack_bf2(hx, hy);
    hv.y = pack_bf2(hz, hw);
    lv.x = pack_bf2(__float2bfloat16(v.x - __bfloat162float(hx)),
                    __float2bfloat16(v.y - __bfloat162float(hy)));
    lv.y = pack_bf2(__float2bfloat16(v.z - __bfloat162float(hz)),
                    __float2bfloat16(v.w - __bfloat162float(hw)));
    *(uint2*)&sAhi[off] = hv;
    *(uint2*)&sAlo[off] = lv;
}

template <bool GATHER>
__global__ __launch_bounds__(256) void gemm_fused_kernel(
    const float* __restrict__ Ain,   // layer-0 x (GATHER=false path)
    int layer,
    const float* __restrict__ bias,  // prev-layer bias (GATHER path)
    int bufsel,
    int n)
{
    __shared__ __nv_bfloat16 sAhi[64 * LDA];
    __shared__ __nv_bfloat16 sAlo[64 * LDA];

    const float* __restrict__ in  = GATHER ? (bufsel ? g_bufB : g_bufA) : Ain;
    float*       __restrict__ outb = bufsel ? g_bufA : g_bufB;
    if (!GATHER) outb = g_bufA;

    int tid = threadIdx.x, lane = tid & 31, wid = tid >> 5;
    int rowBase = blockIdx.x * 64;

    if (GATHER) {
        // ---- phase 1: warp-collective gather-aggregate, 8 rows per warp ----
        float4 bb = *(const float4*)(bias + lane * 4);
        #pragma unroll
        for (int r8 = 0; r8 < 8; r8++) {
            int local = wid * 8 + r8;
            int row = rowBase + local;
            if (row < n) {
                float4 accA = __ldg((const float4*)(in + (size_t)row * F) + lane);
                float4 accB = make_float4(0.f, 0.f, 0.f, 0.f);
                int beg = g_rowstart[row];
                int cnt = g_cnt[row];
                int j = 0;
                for (; j + 3 < cnt; j += 4) {
                    int s0 = __ldg(&g_csrc[beg + j + 0]);
                    int s1 = __ldg(&g_csrc[beg + j + 1]);
                    int s2 = __ldg(&g_csrc[beg + j + 2]);
                    int s3 = __ldg(&g_csrc[beg + j + 3]);
                    float4 v0 = __ldg((const float4*)(in + (size_t)s0 * F) + lane);
                    float4 v1 = __ldg((const float4*)(in + (size_t)s1 * F) + lane);
                    float4 v2 = __ldg((const float4*)(in + (size_t)s2 * F) + lane);
                    float4 v3 = __ldg((const float4*)(in + (size_t)s3 * F) + lane);
                    accA.x += v0.x; accA.y += v0.y; accA.z += v0.z; accA.w += v0.w;
                    accB.x += v1.x; accB.y += v1.y; accB.z += v1.z; accB.w += v1.w;
                    accA.x += v2.x; accA.y += v2.y; accA.z += v2.z; accA.w += v2.w;
                    accB.x += v3.x; accB.y += v3.y; accB.z += v3.z; accB.w += v3.w;
                }
                for (; j < cnt; j++) {
                    int s0 = __ldg(&g_csrc[beg + j]);
                    float4 v0 = __ldg((const float4*)(in + (size_t)s0 * F) + lane);
                    accA.x += v0.x; accA.y += v0.y; accA.z += v0.z; accA.w += v0.w;
                }
                float dw = g_dis[row];
                float4 v;
                v.x = elu_act((accA.x + accB.x) * dw + bb.x);
                v.y = elu_act((accA.y + accB.y) * dw + bb.y);
                v.z = elu_act((accA.z + accB.z) * dw + bb.z);
                v.w = elu_act((accA.w + accB.w) * dw + bb.w);
                split_store(sAhi, sAlo, local * LDA + lane * 4, v);
            } else {
                uint2 z = make_uint2(0u, 0u);
                *(uint2*)&sAhi[local * LDA + lane * 4] = z;
                *(uint2*)&sAlo[local * LDA + lane * 4] = z;
            }
        }
    } else {
        // ---- layer 0: stage directly from x (thread -> row, 32-col seg) ----
        int row  = tid >> 2;
        int cseg = (tid & 3) * 32;
        int grow = rowBase + row;
        if (grow < n) {
            const float4* src = (const float4*)(in + (size_t)grow * F + cseg);
            #pragma unroll
            for (int jj = 0; jj < 8; jj++)
                split_store(sAhi, sAlo, row * LDA + cseg + jj * 4, src[jj]);
        } else {
            uint2 z = make_uint2(0u, 0u);
            #pragma unroll
            for (int jj = 0; jj < 8; jj++) {
                *(uint2*)&sAhi[row * LDA + cseg + jj * 4] = z;
                *(uint2*)&sAlo[row * LDA + cseg + jj * 4] = z;
            }
        }
    }
    __syncthreads();

    // ---- phase 2: 3-term split mma ----
    int mwarp = wid & 1;
    int nwarp = wid >> 1;

    float c[2][4][4];
    #pragma unroll
    for (int mt = 0; mt < 2; mt++)
        #pragma unroll
        for (int nt = 0; nt < 4; nt++)
            #pragma unroll
            for (int q = 0; q < 4; q++) c[mt][nt][q] = 0.0f;

    int lj   = lane >> 3;
    int lrow = (lj & 1) * 8 + (lane & 7);
    int lcol = (lj >> 1) * 8;

    #pragma unroll
    for (int term = 0; term < 3; term++) {
        const __nv_bfloat16* __restrict__ Asrc = (term == 2) ? sAlo : sAhi;
        const uint2* __restrict__ Bsrc = &g_wfrag[layer][term == 1][0][0][0];

        #pragma unroll
        for (int ks = 0; ks < 8; ks++) {
            uint32_t a[2][4];
            #pragma unroll
            for (int mt = 0; mt < 2; mt++) {
                uint32_t addr = smem_u32(
                    &Asrc[(mwarp * 32 + mt * 16 + lrow) * LDA + ks * 16 + lcol]);
                asm volatile(
                    "ldmatrix.sync.aligned.m8n8.x4.shared.b16 {%0,%1,%2,%3}, [%4];"
                    : "=r"(a[mt][0]), "=r"(a[mt][1]), "=r"(a[mt][2]), "=r"(a[mt][3])
                    : "r"(addr));
            }
            uint2 b[4];
            #pragma unroll
            for (int nt = 0; nt < 4; nt++)
                b[nt] = Bsrc[(ks * 16 + nwarp * 4 + nt) * 32 + lane];

            #pragma unroll
            for (int mt = 0; mt < 2; mt++)
                #pragma unroll
                for (int nt = 0; nt < 4; nt++)
                    asm volatile(
                        "mma.sync.aligned.m16n8k16.row.col.f32.bf16.bf16.f32 "
                        "{%0,%1,%2,%3}, {%4,%5,%6,%7}, {%8,%9}, {%0,%1,%2,%3};"
                        : "+f"(c[mt][nt][0]), "+f"(c[mt][nt][1]),
                          "+f"(c[mt][nt][2]), "+f"(c[mt][nt][3])
                        : "r"(a[mt][0]), "r"(a[mt][1]), "r"(a[mt][2]), "r"(a[mt][3]),
                          "r"(b[nt].x), "r"(b[nt].y));
        }
    }

    // ---- epilogue: tmp' = dis[row] * C ----
    int r0 = lane >> 2;
    int c0 = (lane & 3) * 2;
    #pragma unroll
    for (int mt = 0; mt < 2; mt++) {
        int row_a = rowBase + mwarp * 32 + mt * 16 + r0;
        int row_b = row_a + 8;
        float dwa = (row_a < n) ? g_dis[row_a] : 0.0f;
        float dwb = (row_b < n) ? g_dis[row_b] : 0.0f;
        #pragma unroll
        for (int nt = 0; nt < 4; nt++) {
            int col = nwarp * 32 + nt * 8 + c0;
            if (row_a < n)
                *(float2*)&outb[(size_t)row_a * F + col] =
                    make_float2(c[mt][nt][0] * dwa, c[mt][nt][1] * dwa);
            if (row_b < n)
                *(float2*)&outb[(size_t)row_b * F + col] =
                    make_float2(c[mt][nt][2] * dwb, c[mt][nt][3] * dwb);
        }
    }
}

// ---------------- fused final: gather + elu + head ---------------------------
// out[d] = elu(dis[d]*(tmp'[d] + Σ tmp'[s]) + b2) . Wl + bl   (warp per node)
// Reads from g_bufA (layer-2 output).
__global__ __launch_bounds__(256) void final_kernel(
    const float* __restrict__ bias,
    const float* __restrict__ Wl,
    const float* __restrict__ bl,
    float* __restrict__ out, int n)
{
    const float* __restrict__ Aprev = g_bufA;
    int node = blockIdx.x * 8 + (threadIdx.x >> 5);
    int lane = threadIdx.x & 31;
    if (node >= n) return;

    float4 accA = __ldg((const float4*)(Aprev + (size_t)node * F) + lane);
    float4 accB = make_float4(0.f, 0.f, 0.f, 0.f);
    int beg = g_rowstart[node];
    int cnt = g_cnt[node];
    int j = 0;
    for (; j + 3 < cnt; j += 4) {
        int s0 = __ldg(&g_csrc[beg + j + 0]);
        int s1 = __ldg(&g_csrc[beg + j + 1]);
        int s2 = __ldg(&g_csrc[beg + j + 2]);
        int s3 = __ldg(&g_csrc[beg + j + 3]);
        float4 v0 = __ldg((const float4*)(Aprev + (size_t)s0 * F) + lane);
        float4 v1 = __ldg((const float4*)(Aprev + (size_t)s1 * F) + lane);
        float4 v2 = __ldg((const float4*)(Aprev + (size_t)s2 * F) + lane);
        float4 v3 = __ldg((const float4*)(Aprev + (size_t)s3 * F) + lane);
        accA.x += v0.x; accA.y += v0.y; accA.z += v0.z; accA.w += v0.w;
        accB.x += v1.x; accB.y += v1.y; accB.z += v1.z; accB.w += v1.w;
        accA.x += v2.x; accA.y += v2.y; accA.z += v2.z; accA.w += v2.w;
        accB.x += v3.x; accB.y += v3.y; accB.z += v3.z; accB.w += v3.w;
    }
    for (; j < cnt; j++) {
        int s0 = __ldg(&g_csrc[beg + j]);
        float4 v0 = __ldg((const float4*)(Aprev + (size_t)s0 * F) + lane);
        accA.x += v0.x; accA.y += v0.y; accA.z += v0.z; accA.w += v0.w;
    }
    accA.x += accB.x; accA.y += accB.y; accA.z += accB.z; accA.w += accB.w;

    float dw  = g_dis[node];
    float4 bb = *(const float4*)(bias + lane * 4);
    float4 w  = *(const float4*)(Wl + lane * 4);

    float s = elu_act(accA.x * dw + bb.x) * w.x
            + elu_act(accA.y * dw + bb.y) * w.y
            + elu_act(accA.z * dw + bb.z) * w.z
            + elu_act(accA.w * dw + bb.w) * w.w;

    #pragma unroll
    for (int o = 16; o > 0; o >>= 1)
        s += __shfl_xor_sync(0xFFFFFFFFu, s, o);

    if (lane == 0) out[node] = s + bl[0];
}

// ---------------- launch ----------------------------------------------------
extern "C" void kernel_launch(void* const* d_in, const int* in_sizes, int n_in,
                              void* d_out, int out_size)
{
    const float* x   = (const float*)d_in[0];   // [N,128]
    const float* Ws  = (const float*)d_in[1];   // [3,128,128]
    const float* bs  = (const float*)d_in[2];   // [3,128]
    const float* Wl  = (const float*)d_in[3];   // [128,1]
    const float* bl  = (const float*)d_in[4];   // [1]
    const int*   ei  = (const int*)d_in[5];     // [2,E]
    float* out = (float*)d_out;

    int n = in_sizes[0] / F;
    int E = in_sizes[5] / 2;
    if (n > NN) n = NN;
    if (E > EE) E = EE;

    const int TB = 256;
    int nScanBlk = (n + SCAN_B - 1) / SCAN_B;

    // W fragment pre-bake + CSR build (self-loops folded analytically)
    wfrag_kernel<<<(3 * 2 * 8 * 16 * 32 + TB - 1) / TB, TB>>>(Ws);
    init_cnt_kernel<<<(n + TB - 1) / TB, TB>>>(n);
    count_kernel<<<(E + TB - 1) / TB, TB>>>(ei, E);
    scan_blocks_kernel<<<nScanBlk, SCAN_B>>>(n);    // also computes g_dis
    scan_sums_kernel<<<1, 256>>>(nScanBlk);
    scan_add_kernel<<<nScanBlk, SCAN_B>>>(n);
    fill_kernel<<<(E + TB - 1) / TB, TB>>>(ei, E);

    int gemmGrid  = (n + 63) / 64;
    int finGrid   = (n + 7) / 8;

    // layer 0: bufA = dis * (x @ W0)
    gemm_fused_kernel<false><<<gemmGrid, TB>>>(x, 0, nullptr, 0, n);
    // layer 1: bufB = dis * (elu(dis*AGG(bufA) + bs0) @ W1)   (bufsel=0: in A, out B)
    gemm_fused_kernel<true><<<gemmGrid, TB>>>(nullptr, 1, bs + 0 * F, 0, n);
    // layer 2: bufA = dis * (elu(dis*AGG(bufB) + bs1) @ W2)   (bufsel=1: in B, out A)
    gemm_fused_kernel<true><<<gemmGrid, TB>>>(nullptr, 2, bs + 1 * F, 1, n);
    // head: out = elu(dis*AGG(bufA) + bs2) @ Wl + bl
    final_kernel<<<finGrid, TB>>>(bs + 2 * F, Wl, bl, out, n);
}